// round 5
// baseline (speedup 1.0000x reference)
#include <cuda_runtime.h>
#include <math.h>
#include <stdint.h>

#define NTOK 8192
#define DIM 1024

// ---------------- scratch (device globals; no allocation) ----------------
__device__ float g_h[NTOK * DIM];
__device__ float g_qkv[NTOK * 3 * DIM];
__device__ float g_attno[NTOK * DIM];
__device__ float g_x1[NTOK * DIM];
__device__ float g_ff[NTOK * 4096];
// tf32-rounded weight copies
__device__ float g_wq[3 * DIM * DIM];
__device__ float g_wo[DIM * DIM];
__device__ float g_w1[4096 * DIM];
__device__ float g_w2[DIM * 4096];

__device__ __forceinline__ float to_tf32(float x) {
  uint32_t u;
  asm("cvt.rna.tf32.f32 %0, %1;" : "=r"(u) : "f"(x));
  return __uint_as_float(u);
}

__device__ __forceinline__ void cp16(uint32_t dst, const void* src) {
  asm volatile("cp.async.cg.shared.global [%0], [%1], 16;" ::"r"(dst), "l"(src));
}

// ---------------- weight rounding pass ----------------
__global__ void __launch_bounds__(256) round_copy(
    const float* __restrict__ in, float* __restrict__ out, int n4) {
  const int i = blockIdx.x * 256 + threadIdx.x;
  if (i < n4) {
    const float4 v = reinterpret_cast<const float4*>(in)[i];
    float4 o;
    o.x = to_tf32(v.x); o.y = to_tf32(v.y);
    o.z = to_tf32(v.z); o.w = to_tf32(v.w);
    reinterpret_cast<float4*>(out)[i] = o;
  }
}

// ---------------- LayerNorm (tf32-rounded output: feeds GEMM A) -----------
__global__ void __launch_bounds__(256) ln_kernel(
    const float* __restrict__ in, const float* __restrict__ w,
    const float* __restrict__ b, float* __restrict__ out) {
  const int row = blockIdx.x;
  const int tid = threadIdx.x;
  const float4 v = reinterpret_cast<const float4*>(in + (size_t)row * DIM)[tid];
  float s = v.x + v.y + v.z + v.w;
  float sq = v.x * v.x + v.y * v.y + v.z * v.z + v.w * v.w;
#pragma unroll
  for (int o = 16; o > 0; o >>= 1) {
    s += __shfl_xor_sync(0xffffffffu, s, o);
    sq += __shfl_xor_sync(0xffffffffu, sq, o);
  }
  __shared__ float rs[8], rq[8];
  const int warp = tid >> 5, lane = tid & 31;
  if (lane == 0) { rs[warp] = s; rq[warp] = sq; }
  __syncthreads();
  float st = 0.f, sqt = 0.f;
#pragma unroll
  for (int i = 0; i < 8; i++) { st += rs[i]; sqt += rq[i]; }
  const float mu = st * (1.0f / DIM);
  const float var = sqt * (1.0f / DIM) - mu * mu;
  const float rstd = rsqrtf(var + 1e-5f);
  const float4 wv = reinterpret_cast<const float4*>(w)[tid];
  const float4 bv = reinterpret_cast<const float4*>(b)[tid];
  float4 o;
  o.x = to_tf32((v.x - mu) * rstd * wv.x + bv.x);
  o.y = to_tf32((v.y - mu) * rstd * wv.y + bv.y);
  o.z = to_tf32((v.z - mu) * rstd * wv.z + bv.z);
  o.w = to_tf32((v.w - mu) * rstd * wv.w + bv.w);
  reinterpret_cast<float4*>(out + (size_t)row * DIM)[tid] = o;
}

// ---------------- tf32 tensor-core GEMM NT, 3-stage cp.async, swizzled -----
// C[M,N] = A[M,K] @ W[N,K]^T + bias (+epilogue). Inputs pre-rounded to tf32.
// EPI: 0 = bias, 1 = bias + residual, 2 = bias + exact GELU (tf32-rounded out)
// Tile 128x128x32, 8 warps, warp tile 32x64, m16n8k8.
// Smem rows are 32 floats (128B) with SW128 XOR swizzle; every fragment row
// used by a thread is congruent to lg (mod 8), so swizzle term = lg*4 const.
#define STAGE (2 * 128 * 32)            // floats per stage (A + B)
#define MMA_SMEM (3 * STAGE * 4)        // 96 KB

template <int EPI>
__global__ void __launch_bounds__(256, 2) mma_nt(
    const float* __restrict__ A, const float* __restrict__ W,
    const float* __restrict__ bias, const float* __restrict__ res,
    float* __restrict__ C, int M, int N, int K) {
  extern __shared__ float sm[];
  const uint32_t smb = (uint32_t)__cvta_generic_to_shared(sm);

  const int bm = blockIdx.y * 128;
  const int bn = blockIdx.x * 128;
  const int tid = threadIdx.x;
  const int lane = tid & 31;
  const int warp = tid >> 5;
  const int wm = (warp >> 1) * 32;
  const int wn = (warp & 1) * 64;
  const int lg = lane >> 2;
  const int lt = lane & 3;
  const int swz = lg << 2;  // per-thread swizzle term for frag loads

  float acc[2][8][4];
#pragma unroll
  for (int mt = 0; mt < 2; mt++)
#pragma unroll
    for (int nt = 0; nt < 8; nt++)
#pragma unroll
      for (int i = 0; i < 4; i++) acc[mt][nt][i] = 0.f;

  const int lr = tid >> 3;                    // 0..31 (+32*i)
  const int lc4 = (tid & 7) * 4;              // gmem col 0,4,...,28
  const int sc = lc4 ^ ((lr & 7) << 2);       // swizzled smem col
  const int NIT = K >> 5;

  auto load_stage = [&](int s, int k0) {
    const uint32_t abase = smb + (uint32_t)(s * STAGE) * 4u;
    const uint32_t bbase = abase + (uint32_t)(128 * 32) * 4u;
#pragma unroll
    for (int i = 0; i < 4; i++) {
      const int row = lr + i * 32;
      cp16(abase + (uint32_t)(row * 32 + sc) * 4u,
           A + (size_t)(bm + row) * K + k0 + lc4);
      cp16(bbase + (uint32_t)(row * 32 + sc) * 4u,
           W + (size_t)(bn + row) * K + k0 + lc4);
    }
    asm volatile("cp.async.commit_group;");
  };

  load_stage(0, 0);
  load_stage(1, 32);

  for (int it = 0; it < NIT; it++) {
    if (it + 1 < NIT) {
      asm volatile("cp.async.wait_group 1;");
    } else {
      asm volatile("cp.async.wait_group 0;");
    }
    __syncthreads();

    // issue load for stage it+2 (buffer (it+2)%3 is free) before compute
    if (it + 2 < NIT) {
      int s = it + 2;
      s = s - (s / 3) * 3;
      load_stage(s, (it + 2) << 5);
    }

    int cs = it - (it / 3) * 3;
    const float* Ab = sm + cs * STAGE;
    const float* Bb = Ab + 128 * 32;
#pragma unroll
    for (int kk = 0; kk < 4; kk++) {
      const int c0 = (kk * 8 + lt) ^ swz;
      const int c1 = c0 ^ 4;
      uint32_t af[2][4];
#pragma unroll
      for (int mt = 0; mt < 2; mt++) {
        const int rbase = wm + mt * 16;
        af[mt][0] = __float_as_uint(Ab[(rbase + lg) * 32 + c0]);
        af[mt][1] = __float_as_uint(Ab[(rbase + 8 + lg) * 32 + c0]);
        af[mt][2] = __float_as_uint(Ab[(rbase + lg) * 32 + c1]);
        af[mt][3] = __float_as_uint(Ab[(rbase + 8 + lg) * 32 + c1]);
      }
#pragma unroll
      for (int nt = 0; nt < 8; nt++) {
        const int nbase = wn + nt * 8;
        uint32_t b0 = __float_as_uint(Bb[(nbase + lg) * 32 + c0]);
        uint32_t b1 = __float_as_uint(Bb[(nbase + lg) * 32 + c1]);
#pragma unroll
        for (int mt = 0; mt < 2; mt++) {
          asm volatile(
              "mma.sync.aligned.m16n8k8.row.col.f32.tf32.tf32.f32 "
              "{%0,%1,%2,%3}, {%4,%5,%6,%7}, {%8,%9}, {%0,%1,%2,%3};"
              : "+f"(acc[mt][nt][0]), "+f"(acc[mt][nt][1]),
                "+f"(acc[mt][nt][2]), "+f"(acc[mt][nt][3])
              : "r"(af[mt][0]), "r"(af[mt][1]), "r"(af[mt][2]), "r"(af[mt][3]),
                "r"(b0), "r"(b1));
        }
      }
    }
  }

  // epilogue
#pragma unroll
  for (int mt = 0; mt < 2; mt++) {
#pragma unroll
    for (int nt = 0; nt < 8; nt++) {
      const int c0 = bn + wn + nt * 8 + 2 * lt;
      const float2 bb = *reinterpret_cast<const float2*>(bias + c0);
#pragma unroll
      for (int rh = 0; rh < 2; rh++) {
        const int row = bm + wm + mt * 16 + lg + rh * 8;
        float2 o;
        o.x = acc[mt][nt][rh * 2 + 0] + bb.x;
        o.y = acc[mt][nt][rh * 2 + 1] + bb.y;
        if (EPI == 1) {
          const float2 rr = *reinterpret_cast<const float2*>(res + (size_t)row * N + c0);
          o.x += rr.x; o.y += rr.y;
        } else if (EPI == 2) {
          o.x = to_tf32(0.5f * o.x * (1.0f + erff(o.x * 0.70710678118654752f)));
          o.y = to_tf32(0.5f * o.y * (1.0f + erff(o.y * 0.70710678118654752f)));
        }
        *reinterpret_cast<float2*>(C + (size_t)row * N + c0) = o;
      }
    }
  }
}

// ---------------- tf32 tensor-core flash attention (unchanged) -------------
#define QSTR 68
#define VSTR 72
#define ATTN_SMEM ((128 * QSTR + 64 * QSTR + 64 * VSTR + 128 * QSTR) * 4)

__global__ void __launch_bounds__(256) attn_mma(
    const float* __restrict__ qkv, float* __restrict__ out) {
  extern __shared__ float sma[];
  float* const Qs = sma;
  float* const Ks = Qs + 128 * QSTR;
  float* const Vs = Ks + 64 * QSTR;
  float* const Ps = Vs + 64 * VSTR;

  const int tid = threadIdx.x;
  const int lane = tid & 31;
  const int warp = tid >> 5;
  const int lg = lane >> 2;
  const int lt = lane & 3;
  const int bh = blockIdx.y;
  const int b = bh >> 4, h = bh & 15;
  const int q0 = blockIdx.x * 128;
  const size_t base = (size_t)b * 1024 * 3072 + (size_t)h * 64;

  {
    const int row = tid >> 1;
    const int c = (tid & 1) * 32;
    const float* src = qkv + base + (size_t)(q0 + row) * 3072 + c;
    float* dst = Qs + row * QSTR + c;
#pragma unroll
    for (int i = 0; i < 8; i++) {
      const float4 v = *reinterpret_cast<const float4*>(src + i * 4);
      dst[i * 4 + 0] = to_tf32(v.x * 0.125f);
      dst[i * 4 + 1] = to_tf32(v.y * 0.125f);
      dst[i * 4 + 2] = to_tf32(v.z * 0.125f);
      dst[i * 4 + 3] = to_tf32(v.w * 0.125f);
    }
  }

  float m_prev0 = -INFINITY, m_prev1 = -INFINITY;
  float l0 = 0.f, l1 = 0.f;
  float oacc[8][4];
#pragma unroll
  for (int nt = 0; nt < 8; nt++)
#pragma unroll
    for (int i = 0; i < 4; i++) oacc[nt][i] = 0.f;

  float* const Pw = Ps + warp * 16 * QSTR;
  const float* const Qw = Qs + warp * 16 * QSTR;

  for (int t = 0; t < 16; t++) {
    __syncthreads();
    {
      const int row = tid >> 2;
      const int c = (tid & 3) * 16;
      const float* ksrc = qkv + base + (size_t)(t * 64 + row) * 3072 + 1024 + c;
      const float* vsrc = ksrc + 1024;
      float* kd = Ks + row * QSTR + c;
      float* vd = Vs + row * VSTR + c;
#pragma unroll
      for (int i = 0; i < 4; i++) {
        const float4 kv = *reinterpret_cast<const float4*>(ksrc + i * 4);
        kd[i * 4 + 0] = to_tf32(kv.x); kd[i * 4 + 1] = to_tf32(kv.y);
        kd[i * 4 + 2] = to_tf32(kv.z); kd[i * 4 + 3] = to_tf32(kv.w);
        const float4 vv = *reinterpret_cast<const float4*>(vsrc + i * 4);
        vd[i * 4 + 0] = to_tf32(vv.x); vd[i * 4 + 1] = to_tf32(vv.y);
        vd[i * 4 + 2] = to_tf32(vv.z); vd[i * 4 + 3] = to_tf32(vv.w);
      }
    }
    __syncthreads();

    float sacc[8][4];
#pragma unroll
    for (int nt = 0; nt < 8; nt++)
#pragma unroll
      for (int i = 0; i < 4; i++) sacc[nt][i] = 0.f;

#pragma unroll
    for (int kc = 0; kc < 8; kc++) {
      const int k = kc * 8;
      uint32_t a0 = __float_as_uint(Qw[(lg) * QSTR + k + lt]);
      uint32_t a1 = __float_as_uint(Qw[(lg + 8) * QSTR + k + lt]);
      uint32_t a2 = __float_as_uint(Qw[(lg) * QSTR + k + 4 + lt]);
      uint32_t a3 = __float_as_uint(Qw[(lg + 8) * QSTR + k + 4 + lt]);
#pragma unroll
      for (int nt = 0; nt < 8; nt++) {
        uint32_t b0 = __float_as_uint(Ks[(nt * 8 + lg) * QSTR + k + lt]);
        uint32_t b1 = __float_as_uint(Ks[(nt * 8 + lg) * QSTR + k + 4 + lt]);
        asm volatile(
            "mma.sync.aligned.m16n8k8.row.col.f32.tf32.tf32.f32 "
            "{%0,%1,%2,%3}, {%4,%5,%6,%7}, {%8,%9}, {%0,%1,%2,%3};"
            : "+f"(sacc[nt][0]), "+f"(sacc[nt][1]),
              "+f"(sacc[nt][2]), "+f"(sacc[nt][3])
            : "r"(a0), "r"(a1), "r"(a2), "r"(a3), "r"(b0), "r"(b1));
      }
    }

    float mx0 = -INFINITY, mx1 = -INFINITY;
#pragma unroll
    for (int nt = 0; nt < 8; nt++) {
      mx0 = fmaxf(mx0, fmaxf(sacc[nt][0], sacc[nt][1]));
      mx1 = fmaxf(mx1, fmaxf(sacc[nt][2], sacc[nt][3]));
    }
    mx0 = fmaxf(mx0, __shfl_xor_sync(0xffffffffu, mx0, 1));
    mx0 = fmaxf(mx0, __shfl_xor_sync(0xffffffffu, mx0, 2));
    mx1 = fmaxf(mx1, __shfl_xor_sync(0xffffffffu, mx1, 1));
    mx1 = fmaxf(mx1, __shfl_xor_sync(0xffffffffu, mx1, 2));
    const float mnew0 = fmaxf(m_prev0, mx0);
    const float mnew1 = fmaxf(m_prev1, mx1);
    const float f0 = expf(m_prev0 - mnew0);
    const float f1 = expf(m_prev1 - mnew1);
    float rsum0 = 0.f, rsum1 = 0.f;
#pragma unroll
    for (int nt = 0; nt < 8; nt++) {
      const float p0 = to_tf32(expf(sacc[nt][0] - mnew0));
      const float p1 = to_tf32(expf(sacc[nt][1] - mnew0));
      const float p2 = to_tf32(expf(sacc[nt][2] - mnew1));
      const float p3 = to_tf32(expf(sacc[nt][3] - mnew1));
      rsum0 += p0 + p1; rsum1 += p2 + p3;
      sacc[nt][0] = p0; sacc[nt][1] = p1; sacc[nt][2] = p2; sacc[nt][3] = p3;
    }
    rsum0 += __shfl_xor_sync(0xffffffffu, rsum0, 1);
    rsum0 += __shfl_xor_sync(0xffffffffu, rsum0, 2);
    rsum1 += __shfl_xor_sync(0xffffffffu, rsum1, 1);
    rsum1 += __shfl_xor_sync(0xffffffffu, rsum1, 2);
    l0 = l0 * f0 + rsum0;
    l1 = l1 * f1 + rsum1;
    m_prev0 = mnew0; m_prev1 = mnew1;
#pragma unroll
    for (int nt = 0; nt < 8; nt++) {
      oacc[nt][0] *= f0; oacc[nt][1] *= f0;
      oacc[nt][2] *= f1; oacc[nt][3] *= f1;
    }

#pragma unroll
    for (int nt = 0; nt < 8; nt++) {
      *reinterpret_cast<float2*>(Pw + lg * QSTR + nt * 8 + 2 * lt) =
          make_float2(sacc[nt][0], sacc[nt][1]);
      *reinterpret_cast<float2*>(Pw + (lg + 8) * QSTR + nt * 8 + 2 * lt) =
          make_float2(sacc[nt][2], sacc[nt][3]);
    }
    __syncwarp();

#pragma unroll
    for (int cc = 0; cc < 8; cc++) {
      const int c = cc * 8;
      uint32_t a0 = __float_as_uint(Pw[(lg) * QSTR + c + lt]);
      uint32_t a1 = __float_as_uint(Pw[(lg + 8) * QSTR + c + lt]);
      uint32_t a2 = __float_as_uint(Pw[(lg) * QSTR + c + 4 + lt]);
      uint32_t a3 = __float_as_uint(Pw[(lg + 8) * QSTR + c + 4 + lt]);
#pragma unroll
      for (int nt = 0; nt < 8; nt++) {
        uint32_t b0 = __float_as_uint(Vs[(c + lt) * VSTR + nt * 8 + lg]);
        uint32_t b1 = __float_as_uint(Vs[(c + 4 + lt) * VSTR + nt * 8 + lg]);
        asm volatile(
            "mma.sync.aligned.m16n8k8.row.col.f32.tf32.tf32.f32 "
            "{%0,%1,%2,%3}, {%4,%5,%6,%7}, {%8,%9}, {%0,%1,%2,%3};"
            : "+f"(oacc[nt][0]), "+f"(oacc[nt][1]),
              "+f"(oacc[nt][2]), "+f"(oacc[nt][3])
            : "r"(a0), "r"(a1), "r"(a2), "r"(a3), "r"(b0), "r"(b1));
      }
    }
  }

  const float inv0 = 1.0f / l0;
  const float inv1 = 1.0f / l1;
  const int r0 = q0 + warp * 16 + lg;
  const int r1 = r0 + 8;
#pragma unroll
  for (int nt = 0; nt < 8; nt++) {
    const int d = h * 64 + nt * 8 + 2 * lt;
    *reinterpret_cast<float2*>(out + (size_t)(b * 1024 + r0) * 1024 + d) =
        make_float2(to_tf32(oacc[nt][0] * inv0), to_tf32(oacc[nt][1] * inv0));
    *reinterpret_cast<float2*>(out + (size_t)(b * 1024 + r1) * 1024 + d) =
        make_float2(to_tf32(oacc[nt][2] * inv1), to_tf32(oacc[nt][3] * inv1));
  }
}

// ---------------- launch ----------------
extern "C" void kernel_launch(void* const* d_in, const int* in_sizes, int n_in,
                              void* d_out, int out_size) {
  const float* x = (const float*)d_in[0];
  const float* ln1w = (const float*)d_in[1];
  const float* ln1b = (const float*)d_in[2];
  const float* qkvw = (const float*)d_in[3];
  const float* qkvb = (const float*)d_in[4];
  const float* outw = (const float*)d_in[5];
  const float* outb = (const float*)d_in[6];
  const float* ln2w = (const float*)d_in[7];
  const float* ln2b = (const float*)d_in[8];
  const float* fc1w = (const float*)d_in[9];
  const float* fc1b = (const float*)d_in[10];
  const float* fc2w = (const float*)d_in[11];
  const float* fc2b = (const float*)d_in[12];
  float* out = (float*)d_out;

  float *h, *qkv, *attno, *x1, *ff, *wq, *wo, *w1, *w2;
  cudaGetSymbolAddress((void**)&h, g_h);
  cudaGetSymbolAddress((void**)&qkv, g_qkv);
  cudaGetSymbolAddress((void**)&attno, g_attno);
  cudaGetSymbolAddress((void**)&x1, g_x1);
  cudaGetSymbolAddress((void**)&ff, g_ff);
  cudaGetSymbolAddress((void**)&wq, g_wq);
  cudaGetSymbolAddress((void**)&wo, g_wo);
  cudaGetSymbolAddress((void**)&w1, g_w1);
  cudaGetSymbolAddress((void**)&w2, g_w2);

  cudaFuncSetAttribute(attn_mma,
                       cudaFuncAttributeMaxDynamicSharedMemorySize, ATTN_SMEM);
  cudaFuncSetAttribute(mma_nt<0>,
                       cudaFuncAttributeMaxDynamicSharedMemorySize, MMA_SMEM);
  cudaFuncSetAttribute(mma_nt<1>,
                       cudaFuncAttributeMaxDynamicSharedMemorySize, MMA_SMEM);
  cudaFuncSetAttribute(mma_nt<2>,
                       cudaFuncAttributeMaxDynamicSharedMemorySize, MMA_SMEM);

  // weight rounding (tf32-canonical copies)
  round_copy<<<(3 * DIM * DIM / 4 + 255) / 256, 256>>>(qkvw, wq, 3 * DIM * DIM / 4);
  round_copy<<<(DIM * DIM / 4 + 255) / 256, 256>>>(outw, wo, DIM * DIM / 4);
  round_copy<<<(4096 * DIM / 4 + 255) / 256, 256>>>(fc1w, w1, 4096 * DIM / 4);
  round_copy<<<(DIM * 4096 / 4 + 255) / 256, 256>>>(fc2w, w2, DIM * 4096 / 4);

  // LN1
  ln_kernel<<<NTOK, 256>>>(x, ln1w, ln1b, h);
  // QKV: [8192,1024] @ [3072,1024]^T
  mma_nt<0><<<dim3(3072 / 128, NTOK / 128), 256, MMA_SMEM>>>(
      h, wq, qkvb, nullptr, qkv, NTOK, 3072, 1024);
  // attention (tensor core)
  attn_mma<<<dim3(1024 / 128, 128), 256, ATTN_SMEM>>>(qkv, attno);
  // out projection + residual
  mma_nt<1><<<dim3(1024 / 128, NTOK / 128), 256, MMA_SMEM>>>(
      attno, wo, outb, x, x1, NTOK, 1024, 1024);
  // LN2
  ln_kernel<<<NTOK, 256>>>(x1, ln2w, ln2b, h);
  // FC1 + GELU
  mma_nt<2><<<dim3(4096 / 128, NTOK / 128), 256, MMA_SMEM>>>(
      h, w1, fc1b, nullptr, ff, NTOK, 4096, 1024);
  // FC2 + residual -> output
  mma_nt<1><<<dim3(1024 / 128, NTOK / 128), 256, MMA_SMEM>>>(
      ff, w2, fc2b, x1, out, NTOK, 1024, 4096);
}

// round 7
// speedup vs baseline: 1.5991x; 1.5991x over previous
#include <cuda_runtime.h>
#include <cuda_fp16.h>
#include <math.h>
#include <stdint.h>

#define NTOK 8192
#define DIM 1024

// ---------------- scratch (device globals; no allocation) ----------------
__device__ __half g_h[NTOK * DIM];        // LN output (fp16, GEMM A)
__device__ float g_qkv[NTOK * 3 * DIM];   // QKV output (fp32, attention input)
__device__ __half g_attno[NTOK * DIM];    // attention output (fp16, GEMM A)
__device__ float g_x1[NTOK * DIM];        // residual after attention (fp32)
__device__ __half g_ff[NTOK * 4096];      // FC1+GELU output (fp16, GEMM A)
// fp16 weight copies
__device__ __half g_wq[3 * DIM * DIM];
__device__ __half g_wo[DIM * DIM];
__device__ __half g_w1[4096 * DIM];
__device__ __half g_w2[DIM * 4096];

__device__ __forceinline__ float to_tf32(float x) {
  uint32_t u;
  asm("cvt.rna.tf32.f32 %0, %1;" : "=r"(u) : "f"(x));
  return __uint_as_float(u);
}

__device__ __forceinline__ void cp16(uint32_t dst, const void* src) {
  asm volatile("cp.async.cg.shared.global [%0], [%1], 16;" ::"r"(dst), "l"(src));
}

// ---------------- weight conversion: fp32 -> fp16 ----------------
__global__ void __launch_bounds__(256) to_half_kernel(
    const float* __restrict__ in, __half* __restrict__ out, int n4) {
  const int i = blockIdx.x * 256 + threadIdx.x;
  if (i < n4) {
    const float4 v = reinterpret_cast<const float4*>(in)[i];
    __half2 h0 = __floats2half2_rn(v.x, v.y);
    __half2 h1 = __floats2half2_rn(v.z, v.w);
    uint2 pk;
    pk.x = *reinterpret_cast<uint32_t*>(&h0);
    pk.y = *reinterpret_cast<uint32_t*>(&h1);
    reinterpret_cast<uint2*>(out)[i] = pk;
  }
}

// ---------------- LayerNorm (fp16 output: feeds GEMM A) ----------------
__global__ void __launch_bounds__(256) ln_kernel(
    const float* __restrict__ in, const float* __restrict__ w,
    const float* __restrict__ b, __half* __restrict__ out) {
  const int row = blockIdx.x;
  const int tid = threadIdx.x;
  const float4 v = reinterpret_cast<const float4*>(in + (size_t)row * DIM)[tid];
  float s = v.x + v.y + v.z + v.w;
  float sq = v.x * v.x + v.y * v.y + v.z * v.z + v.w * v.w;
#pragma unroll
  for (int o = 16; o > 0; o >>= 1) {
    s += __shfl_xor_sync(0xffffffffu, s, o);
    sq += __shfl_xor_sync(0xffffffffu, sq, o);
  }
  __shared__ float rs[8], rq[8];
  const int warp = tid >> 5, lane = tid & 31;
  if (lane == 0) { rs[warp] = s; rq[warp] = sq; }
  __syncthreads();
  float st = 0.f, sqt = 0.f;
#pragma unroll
  for (int i = 0; i < 8; i++) { st += rs[i]; sqt += rq[i]; }
  const float mu = st * (1.0f / DIM);
  const float var = sqt * (1.0f / DIM) - mu * mu;
  const float rstd = rsqrtf(var + 1e-5f);
  const float4 wv = reinterpret_cast<const float4*>(w)[tid];
  const float4 bv = reinterpret_cast<const float4*>(b)[tid];
  __half2 h0 = __floats2half2_rn((v.x - mu) * rstd * wv.x + bv.x,
                                 (v.y - mu) * rstd * wv.y + bv.y);
  __half2 h1 = __floats2half2_rn((v.z - mu) * rstd * wv.z + bv.z,
                                 (v.w - mu) * rstd * wv.w + bv.w);
  uint2 pk;
  pk.x = *reinterpret_cast<uint32_t*>(&h0);
  pk.y = *reinterpret_cast<uint32_t*>(&h1);
  reinterpret_cast<uint2*>(out + (size_t)row * DIM)[tid] = pk;
}

// ---------------- fp16 tensor-core GEMM NT, cp.async double buffer ---------
// C[M,N] = A[M,K] @ W[N,K]^T + bias (+epilogue). A, W are fp16; accum fp32.
// EPI: 0 = bias -> fp32 out, 1 = bias + residual -> fp32 out,
//      2 = bias + exact GELU -> fp16 out
// Tile 128x128x64, 256 threads (8 warps), warp tile 32x64, m16n8k16.
// Smem row stride 72 halves (144 B): frag LDS conflict-free.
#define HSTR 72
#define HSTAGE (256 * HSTR)             // halves per stage (A 128 rows + B 128 rows)
#define MMA_SMEM (2 * HSTAGE * 2)       // bytes (73728)

template <int EPI, typename TO>
__global__ void __launch_bounds__(256, 2) mma_nt(
    const __half* __restrict__ A, const __half* __restrict__ W,
    const float* __restrict__ bias, const float* __restrict__ res,
    TO* __restrict__ C, int M, int N, int K) {
  extern __shared__ __half smh[];
  const uint32_t smb = (uint32_t)__cvta_generic_to_shared(smh);

  const int bm = blockIdx.y * 128;
  const int bn = blockIdx.x * 128;
  const int tid = threadIdx.x;
  const int lane = tid & 31;
  const int warp = tid >> 5;
  const int wm = (warp >> 1) * 32;
  const int wn = (warp & 1) * 64;
  const int lg = lane >> 2;
  const int lt = lane & 3;

  float acc[2][8][4];
#pragma unroll
  for (int mt = 0; mt < 2; mt++)
#pragma unroll
    for (int nt = 0; nt < 8; nt++)
#pragma unroll
      for (int i = 0; i < 4; i++) acc[mt][nt][i] = 0.f;

  const int lr = tid >> 3;        // row 0..31 (+32*i)
  const int lch = (tid & 7) * 8;  // half-col 0,8,...,56
  const int NIT = K >> 6;         // BK = 64

  auto load_stage = [&](int s, int k0) {
    const uint32_t abase = smb + (uint32_t)(s * HSTAGE) * 2u;
    const uint32_t bbase = abase + (uint32_t)(128 * HSTR) * 2u;
#pragma unroll
    for (int i = 0; i < 4; i++) {
      const int row = lr + i * 32;
      cp16(abase + (uint32_t)(row * HSTR + lch) * 2u,
           A + (size_t)(bm + row) * K + k0 + lch);
      cp16(bbase + (uint32_t)(row * HSTR + lch) * 2u,
           W + (size_t)(bn + row) * K + k0 + lch);
    }
    asm volatile("cp.async.commit_group;");
  };

  load_stage(0, 0);

  for (int it = 0; it < NIT; it++) {
    if (it + 1 < NIT) {
      load_stage((it + 1) & 1, (it + 1) << 6);
      asm volatile("cp.async.wait_group 1;");
    } else {
      asm volatile("cp.async.wait_group 0;");
    }
    __syncthreads();

    const __half* Ab = smh + (it & 1) * HSTAGE;
    const __half* Bb = Ab + 128 * HSTR;
#pragma unroll
    for (int ks = 0; ks < 4; ks++) {
      const int k = ks * 16 + 2 * lt;
      uint32_t af[2][4];
#pragma unroll
      for (int mt = 0; mt < 2; mt++) {
        const int r0 = (wm + mt * 16 + lg) * HSTR;
        const int r1 = r0 + 8 * HSTR;
        af[mt][0] = *reinterpret_cast<const uint32_t*>(Ab + r0 + k);
        af[mt][1] = *reinterpret_cast<const uint32_t*>(Ab + r1 + k);
        af[mt][2] = *reinterpret_cast<const uint32_t*>(Ab + r0 + k + 8);
        af[mt][3] = *reinterpret_cast<const uint32_t*>(Ab + r1 + k + 8);
      }
#pragma unroll
      for (int nt = 0; nt < 8; nt++) {
        const int rn = (wn + nt * 8 + lg) * HSTR;
        uint32_t b0 = *reinterpret_cast<const uint32_t*>(Bb + rn + k);
        uint32_t b1 = *reinterpret_cast<const uint32_t*>(Bb + rn + k + 8);
#pragma unroll
        for (int mt = 0; mt < 2; mt++) {
          asm volatile(
              "mma.sync.aligned.m16n8k16.row.col.f32.f16.f16.f32 "
              "{%0,%1,%2,%3}, {%4,%5,%6,%7}, {%8,%9}, {%0,%1,%2,%3};"
              : "+f"(acc[mt][nt][0]), "+f"(acc[mt][nt][1]),
                "+f"(acc[mt][nt][2]), "+f"(acc[mt][nt][3])
              : "r"(af[mt][0]), "r"(af[mt][1]), "r"(af[mt][2]), "r"(af[mt][3]),
                "r"(b0), "r"(b1));
        }
      }
    }
    __syncthreads();
  }

  // epilogue
#pragma unroll
  for (int mt = 0; mt < 2; mt++) {
#pragma unroll
    for (int nt = 0; nt < 8; nt++) {
      const int c0 = bn + wn + nt * 8 + 2 * lt;
      const float2 bb = *reinterpret_cast<const float2*>(bias + c0);
#pragma unroll
      for (int rh = 0; rh < 2; rh++) {
        const int row = bm + wm + mt * 16 + lg + rh * 8;
        float ox = acc[mt][nt][rh * 2 + 0] + bb.x;
        float oy = acc[mt][nt][rh * 2 + 1] + bb.y;
        if (EPI == 1) {
          const float2 rr = *reinterpret_cast<const float2*>(res + (size_t)row * N + c0);
          ox += rr.x; oy += rr.y;
        } else if (EPI == 2) {
          ox = 0.5f * ox * (1.0f + erff(ox * 0.70710678118654752f));
          oy = 0.5f * oy * (1.0f + erff(oy * 0.70710678118654752f));
        }
        if (EPI == 2) {
          __half2 hv = __floats2half2_rn(ox, oy);
          *reinterpret_cast<__half2*>((__half*)C + (size_t)row * N + c0) = hv;
        } else {
          *reinterpret_cast<float2*>((float*)C + (size_t)row * N + c0) =
              make_float2(ox, oy);
        }
      }
    }
  }
}

// ---------------- tf32 tensor-core flash attention (fp16 output) -----------
#define QSTR 68
#define VSTR 72
#define ATTN_SMEM ((128 * QSTR + 64 * QSTR + 64 * VSTR + 128 * QSTR) * 4)

__global__ void __launch_bounds__(256) attn_mma(
    const float* __restrict__ qkv, __half* __restrict__ out) {
  extern __shared__ float sma[];
  float* const Qs = sma;
  float* const Ks = Qs + 128 * QSTR;
  float* const Vs = Ks + 64 * QSTR;
  float* const Ps = Vs + 64 * VSTR;

  const int tid = threadIdx.x;
  const int lane = tid & 31;
  const int warp = tid >> 5;
  const int lg = lane >> 2;
  const int lt = lane & 3;
  const int bh = blockIdx.y;
  const int b = bh >> 4, h = bh & 15;
  const int q0 = blockIdx.x * 128;
  const size_t base = (size_t)b * 1024 * 3072 + (size_t)h * 64;

  {
    const int row = tid >> 1;
    const int c = (tid & 1) * 32;
    const float* src = qkv + base + (size_t)(q0 + row) * 3072 + c;
    float* dst = Qs + row * QSTR + c;
#pragma unroll
    for (int i = 0; i < 8; i++) {
      const float4 v = *reinterpret_cast<const float4*>(src + i * 4);
      dst[i * 4 + 0] = to_tf32(v.x * 0.125f);
      dst[i * 4 + 1] = to_tf32(v.y * 0.125f);
      dst[i * 4 + 2] = to_tf32(v.z * 0.125f);
      dst[i * 4 + 3] = to_tf32(v.w * 0.125f);
    }
  }

  float m_prev0 = -INFINITY, m_prev1 = -INFINITY;
  float l0 = 0.f, l1 = 0.f;
  float oacc[8][4];
#pragma unroll
  for (int nt = 0; nt < 8; nt++)
#pragma unroll
    for (int i = 0; i < 4; i++) oacc[nt][i] = 0.f;

  float* const Pw = Ps + warp * 16 * QSTR;
  const float* const Qw = Qs + warp * 16 * QSTR;

  for (int t = 0; t < 16; t++) {
    __syncthreads();
    {
      const int row = tid >> 2;
      const int c = (tid & 3) * 16;
      const float* ksrc = qkv + base + (size_t)(t * 64 + row) * 3072 + 1024 + c;
      const float* vsrc = ksrc + 1024;
      float* kd = Ks + row * QSTR + c;
      float* vd = Vs + row * VSTR + c;
#pragma unroll
      for (int i = 0; i < 4; i++) {
        const float4 kv = *reinterpret_cast<const float4*>(ksrc + i * 4);
        kd[i * 4 + 0] = to_tf32(kv.x); kd[i * 4 + 1] = to_tf32(kv.y);
        kd[i * 4 + 2] = to_tf32(kv.z); kd[i * 4 + 3] = to_tf32(kv.w);
        const float4 vv = *reinterpret_cast<const float4*>(vsrc + i * 4);
        vd[i * 4 + 0] = to_tf32(vv.x); vd[i * 4 + 1] = to_tf32(vv.y);
        vd[i * 4 + 2] = to_tf32(vv.z); vd[i * 4 + 3] = to_tf32(vv.w);
      }
    }
    __syncthreads();

    float sacc[8][4];
#pragma unroll
    for (int nt = 0; nt < 8; nt++)
#pragma unroll
      for (int i = 0; i < 4; i++) sacc[nt][i] = 0.f;

#pragma unroll
    for (int kc = 0; kc < 8; kc++) {
      const int k = kc * 8;
      uint32_t a0 = __float_as_uint(Qw[(lg) * QSTR + k + lt]);
      uint32_t a1 = __float_as_uint(Qw[(lg + 8) * QSTR + k + lt]);
      uint32_t a2 = __float_as_uint(Qw[(lg) * QSTR + k + 4 + lt]);
      uint32_t a3 = __float_as_uint(Qw[(lg + 8) * QSTR + k + 4 + lt]);
#pragma unroll
      for (int nt = 0; nt < 8; nt++) {
        uint32_t b0 = __float_as_uint(Ks[(nt * 8 + lg) * QSTR + k + lt]);
        uint32_t b1 = __float_as_uint(Ks[(nt * 8 + lg) * QSTR + k + 4 + lt]);
        asm volatile(
            "mma.sync.aligned.m16n8k8.row.col.f32.tf32.tf32.f32 "
            "{%0,%1,%2,%3}, {%4,%5,%6,%7}, {%8,%9}, {%0,%1,%2,%3};"
            : "+f"(sacc[nt][0]), "+f"(sacc[nt][1]),
              "+f"(sacc[nt][2]), "+f"(sacc[nt][3])
            : "r"(a0), "r"(a1), "r"(a2), "r"(a3), "r"(b0), "r"(b1));
      }
    }

    float mx0 = -INFINITY, mx1 = -INFINITY;
#pragma unroll
    for (int nt = 0; nt < 8; nt++) {
      mx0 = fmaxf(mx0, fmaxf(sacc[nt][0], sacc[nt][1]));
      mx1 = fmaxf(mx1, fmaxf(sacc[nt][2], sacc[nt][3]));
    }
    mx0 = fmaxf(mx0, __shfl_xor_sync(0xffffffffu, mx0, 1));
    mx0 = fmaxf(mx0, __shfl_xor_sync(0xffffffffu, mx0, 2));
    mx1 = fmaxf(mx1, __shfl_xor_sync(0xffffffffu, mx1, 1));
    mx1 = fmaxf(mx1, __shfl_xor_sync(0xffffffffu, mx1, 2));
    const float mnew0 = fmaxf(m_prev0, mx0);
    const float mnew1 = fmaxf(m_prev1, mx1);
    const float f0 = expf(m_prev0 - mnew0);
    const float f1 = expf(m_prev1 - mnew1);
    float rsum0 = 0.f, rsum1 = 0.f;
#pragma unroll
    for (int nt = 0; nt < 8; nt++) {
      const float p0 = to_tf32(expf(sacc[nt][0] - mnew0));
      const float p1 = to_tf32(expf(sacc[nt][1] - mnew0));
      const float p2 = to_tf32(expf(sacc[nt][2] - mnew1));
      const float p3 = to_tf32(expf(sacc[nt][3] - mnew1));
      rsum0 += p0 + p1; rsum1 += p2 + p3;
      sacc[nt][0] = p0; sacc[nt][1] = p1; sacc[nt][2] = p2; sacc[nt][3] = p3;
    }
    rsum0 += __shfl_xor_sync(0xffffffffu, rsum0, 1);
    rsum0 += __shfl_xor_sync(0xffffffffu, rsum0, 2);
    rsum1 += __shfl_xor_sync(0xffffffffu, rsum1, 1);
    rsum1 += __shfl_xor_sync(0xffffffffu, rsum1, 2);
    l0 = l0 * f0 + rsum0;
    l1 = l1 * f1 + rsum1;
    m_prev0 = mnew0; m_prev1 = mnew1;
#pragma unroll
    for (int nt = 0; nt < 8; nt++) {
      oacc[nt][0] *= f0; oacc[nt][1] *= f0;
      oacc[nt][2] *= f1; oacc[nt][3] *= f1;
    }

#pragma unroll
    for (int nt = 0; nt < 8; nt++) {
      *reinterpret_cast<float2*>(Pw + lg * QSTR + nt * 8 + 2 * lt) =
          make_float2(sacc[nt][0], sacc[nt][1]);
      *reinterpret_cast<float2*>(Pw + (lg + 8) * QSTR + nt * 8 + 2 * lt) =
          make_float2(sacc[nt][2], sacc[nt][3]);
    }
    __syncwarp();

#pragma unroll
    for (int cc = 0; cc < 8; cc++) {
      const int c = cc * 8;
      uint32_t a0 = __float_as_uint(Pw[(lg) * QSTR + c + lt]);
      uint32_t a1 = __float_as_uint(Pw[(lg + 8) * QSTR + c + lt]);
      uint32_t a2 = __float_as_uint(Pw[(lg) * QSTR + c + 4 + lt]);
      uint32_t a3 = __float_as_uint(Pw[(lg + 8) * QSTR + c + 4 + lt]);
#pragma unroll
      for (int nt = 0; nt < 8; nt++) {
        uint32_t b0 = __float_as_uint(Vs[(c + lt) * VSTR + nt * 8 + lg]);
        uint32_t b1 = __float_as_uint(Vs[(c + 4 + lt) * VSTR + nt * 8 + lg]);
        asm volatile(
            "mma.sync.aligned.m16n8k8.row.col.f32.tf32.tf32.f32 "
            "{%0,%1,%2,%3}, {%4,%5,%6,%7}, {%8,%9}, {%0,%1,%2,%3};"
            : "+f"(oacc[nt][0]), "+f"(oacc[nt][1]),
              "+f"(oacc[nt][2]), "+f"(oacc[nt][3])
            : "r"(a0), "r"(a1), "r"(a2), "r"(a3), "r"(b0), "r"(b1));
      }
    }
  }

  const float inv0 = 1.0f / l0;
  const float inv1 = 1.0f / l1;
  const int r0 = q0 + warp * 16 + lg;
  const int r1 = r0 + 8;
#pragma unroll
  for (int nt = 0; nt < 8; nt++) {
    const int d = h * 64 + nt * 8 + 2 * lt;
    *reinterpret_cast<__half2*>(out + (size_t)(b * 1024 + r0) * 1024 + d) =
        __floats2half2_rn(oacc[nt][0] * inv0, oacc[nt][1] * inv0);
    *reinterpret_cast<__half2*>(out + (size_t)(b * 1024 + r1) * 1024 + d) =
        __floats2half2_rn(oacc[nt][2] * inv1, oacc[nt][3] * inv1);
  }
}

// ---------------- launch ----------------
extern "C" void kernel_launch(void* const* d_in, const int* in_sizes, int n_in,
                              void* d_out, int out_size) {
  const float* x = (const float*)d_in[0];
  const float* ln1w = (const float*)d_in[1];
  const float* ln1b = (const float*)d_in[2];
  const float* qkvw = (const float*)d_in[3];
  const float* qkvb = (const float*)d_in[4];
  const float* outw = (const float*)d_in[5];
  const float* outb = (const float*)d_in[6];
  const float* ln2w = (const float*)d_in[7];
  const float* ln2b = (const float*)d_in[8];
  const float* fc1w = (const float*)d_in[9];
  const float* fc1b = (const float*)d_in[10];
  const float* fc2w = (const float*)d_in[11];
  const float* fc2b = (const float*)d_in[12];
  float* out = (float*)d_out;

  __half *h, *attno, *ff, *wq, *wo, *w1, *w2;
  float *qkv, *x1;
  cudaGetSymbolAddress((void**)&h, g_h);
  cudaGetSymbolAddress((void**)&qkv, g_qkv);
  cudaGetSymbolAddress((void**)&attno, g_attno);
  cudaGetSymbolAddress((void**)&x1, g_x1);
  cudaGetSymbolAddress((void**)&ff, g_ff);
  cudaGetSymbolAddress((void**)&wq, g_wq);
  cudaGetSymbolAddress((void**)&wo, g_wo);
  cudaGetSymbolAddress((void**)&w1, g_w1);
  cudaGetSymbolAddress((void**)&w2, g_w2);

  cudaFuncSetAttribute(attn_mma,
                       cudaFuncAttributeMaxDynamicSharedMemorySize, ATTN_SMEM);
  cudaFuncSetAttribute((const void*)mma_nt<0, float>,
                       cudaFuncAttributeMaxDynamicSharedMemorySize, MMA_SMEM);
  cudaFuncSetAttribute((const void*)mma_nt<1, float>,
                       cudaFuncAttributeMaxDynamicSharedMemorySize, MMA_SMEM);
  cudaFuncSetAttribute((const void*)mma_nt<2, __half>,
                       cudaFuncAttributeMaxDynamicSharedMemorySize, MMA_SMEM);

  // fp16 weight copies
  to_half_kernel<<<(3 * DIM * DIM / 4 + 255) / 256, 256>>>(qkvw, wq, 3 * DIM * DIM / 4);
  to_half_kernel<<<(DIM * DIM / 4 + 255) / 256, 256>>>(outw, wo, DIM * DIM / 4);
  to_half_kernel<<<(4096 * DIM / 4 + 255) / 256, 256>>>(fc1w, w1, 4096 * DIM / 4);
  to_half_kernel<<<(DIM * 4096 / 4 + 255) / 256, 256>>>(fc2w, w2, DIM * 4096 / 4);

  // LN1 -> fp16
  ln_kernel<<<NTOK, 256>>>(x, ln1w, ln1b, h);
  // QKV: [8192,1024] @ [3072,1024]^T -> fp32
  mma_nt<0, float><<<dim3(3072 / 128, NTOK / 128), 256, MMA_SMEM>>>(
      h, wq, qkvb, nullptr, qkv, NTOK, 3072, 1024);
  // attention -> fp16
  attn_mma<<<dim3(1024 / 128, 128), 256, ATTN_SMEM>>>(qkv, attno);
  // out projection + residual -> fp32
  mma_nt<1, float><<<dim3(1024 / 128, NTOK / 128), 256, MMA_SMEM>>>(
      attno, wo, outb, x, x1, NTOK, 1024, 1024);
  // LN2 -> fp16
  ln_kernel<<<NTOK, 256>>>(x1, ln2w, ln2b, h);
  // FC1 + GELU -> fp16
  mma_nt<2, __half><<<dim3(4096 / 128, NTOK / 128), 256, MMA_SMEM>>>(
      h, w1, fc1b, nullptr, ff, NTOK, 4096, 1024);
  // FC2 + residual -> fp32 output
  mma_nt<1, float><<<dim3(1024 / 128, NTOK / 128), 256, MMA_SMEM>>>(
      ff, w2, fc2b, x1, out, NTOK, 1024, 4096);
}

// round 8
// speedup vs baseline: 2.0137x; 1.2593x over previous
#include <cuda_runtime.h>
#include <cuda_fp16.h>
#include <math.h>
#include <stdint.h>

#define NTOK 8192
#define DIM 1024

// ---------------- scratch (device globals; no allocation) ----------------
__device__ __half g_h[NTOK * DIM];          // LN output (fp16, GEMM A)
__device__ __half g_qkv[NTOK * 3 * DIM];    // QKV output (fp16)
__device__ __half g_attno[NTOK * DIM];      // attention output (fp16, GEMM A)
__device__ float g_x1[NTOK * DIM];          // residual after attention (fp32)
__device__ __half g_ff[NTOK * 4096];        // FC1+GELU output (fp16, GEMM A)
__device__ __half g_wq[3 * DIM * DIM];
__device__ __half g_wo[DIM * DIM];
__device__ __half g_w1[4096 * DIM];
__device__ __half g_w2[DIM * 4096];

__device__ __forceinline__ void cp16(uint32_t dst, const void* src) {
  asm volatile("cp.async.cg.shared.global [%0], [%1], 16;" ::"r"(dst), "l"(src));
}

__device__ __forceinline__ void ldsm4(uint32_t& r0, uint32_t& r1, uint32_t& r2,
                                      uint32_t& r3, uint32_t addr) {
  asm volatile(
      "ldmatrix.sync.aligned.m8n8.x4.shared.b16 {%0,%1,%2,%3}, [%4];"
      : "=r"(r0), "=r"(r1), "=r"(r2), "=r"(r3)
      : "r"(addr));
}

#define HMMA16(d, a0, a1, a2, a3, b0, b1)                                    \
  asm volatile(                                                              \
      "mma.sync.aligned.m16n8k16.row.col.f32.f16.f16.f32 "                   \
      "{%0,%1,%2,%3}, {%4,%5,%6,%7}, {%8,%9}, {%0,%1,%2,%3};"                \
      : "+f"((d)[0]), "+f"((d)[1]), "+f"((d)[2]), "+f"((d)[3])               \
      : "r"(a0), "r"(a1), "r"(a2), "r"(a3), "r"(b0), "r"(b1))

// ---------------- weight conversion: fp32 -> fp16 ----------------
__global__ void __launch_bounds__(256) to_half_kernel(
    const float* __restrict__ in, __half* __restrict__ out, int n4) {
  const int i = blockIdx.x * 256 + threadIdx.x;
  if (i < n4) {
    const float4 v = reinterpret_cast<const float4*>(in)[i];
    __half2 h0 = __floats2half2_rn(v.x, v.y);
    __half2 h1 = __floats2half2_rn(v.z, v.w);
    uint2 pk;
    pk.x = *reinterpret_cast<uint32_t*>(&h0);
    pk.y = *reinterpret_cast<uint32_t*>(&h1);
    reinterpret_cast<uint2*>(out)[i] = pk;
  }
}

// ---------------- LayerNorm (fp16 output) ----------------
__global__ void __launch_bounds__(256) ln_kernel(
    const float* __restrict__ in, const float* __restrict__ w,
    const float* __restrict__ b, __half* __restrict__ out) {
  const int row = blockIdx.x;
  const int tid = threadIdx.x;
  const float4 v = reinterpret_cast<const float4*>(in + (size_t)row * DIM)[tid];
  float s = v.x + v.y + v.z + v.w;
  float sq = v.x * v.x + v.y * v.y + v.z * v.z + v.w * v.w;
#pragma unroll
  for (int o = 16; o > 0; o >>= 1) {
    s += __shfl_xor_sync(0xffffffffu, s, o);
    sq += __shfl_xor_sync(0xffffffffu, sq, o);
  }
  __shared__ float rs[8], rq[8];
  const int warp = tid >> 5, lane = tid & 31;
  if (lane == 0) { rs[warp] = s; rq[warp] = sq; }
  __syncthreads();
  float st = 0.f, sqt = 0.f;
#pragma unroll
  for (int i = 0; i < 8; i++) { st += rs[i]; sqt += rq[i]; }
  const float mu = st * (1.0f / DIM);
  const float var = sqt * (1.0f / DIM) - mu * mu;
  const float rstd = rsqrtf(var + 1e-5f);
  const float4 wv = reinterpret_cast<const float4*>(w)[tid];
  const float4 bv = reinterpret_cast<const float4*>(b)[tid];
  __half2 h0 = __floats2half2_rn((v.x - mu) * rstd * wv.x + bv.x,
                                 (v.y - mu) * rstd * wv.y + bv.y);
  __half2 h1 = __floats2half2_rn((v.z - mu) * rstd * wv.z + bv.z,
                                 (v.w - mu) * rstd * wv.w + bv.w);
  uint2 pk;
  pk.x = *reinterpret_cast<uint32_t*>(&h0);
  pk.y = *reinterpret_cast<uint32_t*>(&h1);
  reinterpret_cast<uint2*>(out + (size_t)row * DIM)[tid] = pk;
}

// ---------------- fp16 GEMM NT with ldmatrix + cp.async double buffer ------
// EPI: 0 = bias, 1 = bias + residual(fp32), 2 = bias + exact GELU
// TO = __half or float (output type). Tile 128x128x64, 8 warps, m16n8k16.
#define HSTR 72
#define HSTAGE (256 * HSTR)
#define MMA_SMEM (2 * HSTAGE * 2)

template <int EPI, typename TO>
__global__ void __launch_bounds__(256, 2) mma_nt(
    const __half* __restrict__ A, const __half* __restrict__ W,
    const float* __restrict__ bias, const float* __restrict__ res,
    TO* __restrict__ C, int M, int N, int K) {
  extern __shared__ __half smh[];
  const uint32_t smb = (uint32_t)__cvta_generic_to_shared(smh);

  const int bm = blockIdx.y * 128;
  const int bn = blockIdx.x * 128;
  const int tid = threadIdx.x;
  const int lane = tid & 31;
  const int warp = tid >> 5;
  const int wm = (warp >> 1) * 32;
  const int wn = (warp & 1) * 64;
  const int lg = lane >> 2;
  const int lt = lane & 3;

  float acc[2][8][4];
#pragma unroll
  for (int mt = 0; mt < 2; mt++)
#pragma unroll
    for (int nt = 0; nt < 8; nt++)
#pragma unroll
      for (int i = 0; i < 4; i++) acc[mt][nt][i] = 0.f;

  // ldmatrix per-thread byte offsets (within a stage buffer)
  const uint32_t aoff =
      (uint32_t)(((wm + (lane & 15)) * HSTR + ((lane >> 4) & 1) * 8) * 2);
  uint32_t boff[4];
#pragma unroll
  for (int j = 0; j < 4; j++)
    boff[j] = (uint32_t)(((wn + j * 16 + ((lane >> 4) & 1) * 8 + (lane & 7)) * HSTR +
                          ((lane >> 3) & 1) * 8) * 2) +
              (uint32_t)(128 * HSTR * 2);  // B region offset

  const int lr = tid >> 3;
  const int lch = (tid & 7) * 8;
  const int NIT = K >> 6;

  auto load_stage = [&](int s, int k0) {
    const uint32_t abase = smb + (uint32_t)(s * HSTAGE) * 2u;
    const uint32_t bbase = abase + (uint32_t)(128 * HSTR) * 2u;
#pragma unroll
    for (int i = 0; i < 4; i++) {
      const int row = lr + i * 32;
      cp16(abase + (uint32_t)(row * HSTR + lch) * 2u,
           A + (size_t)(bm + row) * K + k0 + lch);
      cp16(bbase + (uint32_t)(row * HSTR + lch) * 2u,
           W + (size_t)(bn + row) * K + k0 + lch);
    }
    asm volatile("cp.async.commit_group;");
  };

  load_stage(0, 0);

  for (int it = 0; it < NIT; it++) {
    if (it + 1 < NIT) {
      load_stage((it + 1) & 1, (it + 1) << 6);
      asm volatile("cp.async.wait_group 1;");
    } else {
      asm volatile("cp.async.wait_group 0;");
    }
    __syncthreads();

    const uint32_t buf = smb + (uint32_t)((it & 1) * HSTAGE) * 2u;
#pragma unroll
    for (int ks = 0; ks < 4; ks++) {
      const uint32_t kb = (uint32_t)(ks * 32);  // 16 halves
      uint32_t a[2][4];
      ldsm4(a[0][0], a[0][1], a[0][2], a[0][3], buf + aoff + kb);
      ldsm4(a[1][0], a[1][1], a[1][2], a[1][3],
            buf + aoff + kb + (uint32_t)(16 * HSTR * 2));
#pragma unroll
      for (int j = 0; j < 4; j++) {
        uint32_t b0, b1, b2, b3;
        ldsm4(b0, b1, b2, b3, buf + boff[j] + kb);
#pragma unroll
        for (int mt = 0; mt < 2; mt++) {
          HMMA16(acc[mt][2 * j + 0], a[mt][0], a[mt][1], a[mt][2], a[mt][3], b0, b1);
          HMMA16(acc[mt][2 * j + 1], a[mt][0], a[mt][1], a[mt][2], a[mt][3], b2, b3);
        }
      }
    }
    __syncthreads();
  }

  // epilogue
#pragma unroll
  for (int mt = 0; mt < 2; mt++) {
#pragma unroll
    for (int nt = 0; nt < 8; nt++) {
      const int c0 = bn + wn + nt * 8 + 2 * lt;
      const float2 bb = *reinterpret_cast<const float2*>(bias + c0);
#pragma unroll
      for (int rh = 0; rh < 2; rh++) {
        const int row = bm + wm + mt * 16 + lg + rh * 8;
        float ox = acc[mt][nt][rh * 2 + 0] + bb.x;
        float oy = acc[mt][nt][rh * 2 + 1] + bb.y;
        if (EPI == 1) {
          const float2 rr = *reinterpret_cast<const float2*>(res + (size_t)row * N + c0);
          ox += rr.x; oy += rr.y;
        } else if (EPI == 2) {
          ox = 0.5f * ox * (1.0f + erff(ox * 0.70710678118654752f));
          oy = 0.5f * oy * (1.0f + erff(oy * 0.70710678118654752f));
        }
        if (sizeof(TO) == 2) {
          __half2 hv = __floats2half2_rn(ox, oy);
          *reinterpret_cast<__half2*>((__half*)C + (size_t)row * N + c0) = hv;
        } else {
          *reinterpret_cast<float2*>((float*)C + (size_t)row * N + c0) =
              make_float2(ox, oy);
        }
      }
    }
  }
}

// ---------------- fp16 flash attention with ldmatrix ----------------
// CTA: 256 threads, 128 q rows (16/warp), kv tiles of 64, m16n8k16.
// Q pre-scaled by 0.125 (exact in fp16). V stored d-major (transposed).
#define AQ 72
#define ATTN_SMEM ((128 * AQ + 64 * AQ + 64 * AQ + 128 * AQ) * 2)

__global__ void __launch_bounds__(256) attn_h(
    const __half* __restrict__ qkv, __half* __restrict__ out) {
  extern __shared__ __half smh[];
  const uint32_t smb = (uint32_t)__cvta_generic_to_shared(smh);
  const uint32_t qb = smb;
  const uint32_t kb = qb + 128 * AQ * 2;
  const uint32_t vb = kb + 64 * AQ * 2;
  const uint32_t pb = vb + 64 * AQ * 2;
  __half* const Qh = smh;
  __half* const Kh = Qh + 128 * AQ;
  __half* const Vt = Kh + 64 * AQ;
  __half* const Ph = Vt + 64 * AQ;

  const int tid = threadIdx.x;
  const int lane = tid & 31;
  const int warp = tid >> 5;
  const int lg = lane >> 2;
  const int lt = lane & 3;
  const int bh = blockIdx.y;
  const int b = bh >> 4, h = bh & 15;
  const int q0 = blockIdx.x * 128;
  const size_t base = (size_t)b * 1024 * 3072 + (size_t)h * 64;

  // ldmatrix per-thread offsets
  const uint32_t arow_off =
      (uint32_t)(((warp * 16 + (lane & 15)) * AQ + ((lane >> 4) & 1) * 8) * 2);
  uint32_t brow_off[4];
#pragma unroll
  for (int j = 0; j < 4; j++)
    brow_off[j] = (uint32_t)(((j * 16 + ((lane >> 4) & 1) * 8 + (lane & 7)) * AQ +
                              ((lane >> 3) & 1) * 8) * 2);

  // load Q tile [128 x 64], scale by 0.125 (exact)
  {
    const int row = tid >> 1;
    const int c = (tid & 1) * 32;
    const __half2 sc = __float2half2_rn(0.125f);
    const __half* src = qkv + base + (size_t)(q0 + row) * 3072 + c;
    __half* dst = Qh + row * AQ + c;
#pragma unroll
    for (int i = 0; i < 4; i++) {
      uint4 v = *reinterpret_cast<const uint4*>(src + i * 8);
      __half2* p = reinterpret_cast<__half2*>(&v);
      p[0] = __hmul2(p[0], sc); p[1] = __hmul2(p[1], sc);
      p[2] = __hmul2(p[2], sc); p[3] = __hmul2(p[3], sc);
      *reinterpret_cast<uint4*>(dst + i * 8) = v;
    }
  }

  float m_prev0 = -INFINITY, m_prev1 = -INFINITY;
  float l0 = 0.f, l1 = 0.f;
  float oacc[8][4];
#pragma unroll
  for (int nt = 0; nt < 8; nt++)
#pragma unroll
    for (int i = 0; i < 4; i++) oacc[nt][i] = 0.f;

  for (int t = 0; t < 16; t++) {
    __syncthreads();
    // load K [64 x 64] row-major, V transposed -> Vt[d][kv]
    {
      const int row = tid >> 2;          // kv 0..63
      const int c = (tid & 3) * 16;      // d 0,16,32,48
      const __half* ksrc = qkv + base + (size_t)(t * 64 + row) * 3072 + 1024 + c;
      const __half* vsrc = ksrc + 1024;
      *reinterpret_cast<uint4*>(Kh + row * AQ + c) =
          *reinterpret_cast<const uint4*>(ksrc);
      *reinterpret_cast<uint4*>(Kh + row * AQ + c + 8) =
          *reinterpret_cast<const uint4*>(vsrc - 1024 + 8);
      uint4 v0 = *reinterpret_cast<const uint4*>(vsrc);
      uint4 v1 = *reinterpret_cast<const uint4*>(vsrc + 8);
      const __half* hv0 = reinterpret_cast<const __half*>(&v0);
      const __half* hv1 = reinterpret_cast<const __half*>(&v1);
#pragma unroll
      for (int i = 0; i < 8; i++) Vt[(c + i) * AQ + row] = hv0[i];
#pragma unroll
      for (int i = 0; i < 8; i++) Vt[(c + 8 + i) * AQ + row] = hv1[i];
    }
    __syncthreads();

    // S = Q K^T  (warp: 16 x 64)
    float sacc[8][4];
#pragma unroll
    for (int nt = 0; nt < 8; nt++)
#pragma unroll
      for (int i = 0; i < 4; i++) sacc[nt][i] = 0.f;

#pragma unroll
    for (int kc = 0; kc < 4; kc++) {
      const uint32_t kboff = (uint32_t)(kc * 32);
      uint32_t a0, a1, a2, a3;
      ldsm4(a0, a1, a2, a3, qb + arow_off + kboff);
#pragma unroll
      for (int j = 0; j < 4; j++) {
        uint32_t b0, b1, b2, b3;
        ldsm4(b0, b1, b2, b3, kb + brow_off[j] + kboff);
        HMMA16(sacc[2 * j + 0], a0, a1, a2, a3, b0, b1);
        HMMA16(sacc[2 * j + 1], a0, a1, a2, a3, b2, b3);
      }
    }

    // online softmax (rows lg / lg+8; reduce over 4 lanes lt)
    float mx0 = -INFINITY, mx1 = -INFINITY;
#pragma unroll
    for (int nt = 0; nt < 8; nt++) {
      mx0 = fmaxf(mx0, fmaxf(sacc[nt][0], sacc[nt][1]));
      mx1 = fmaxf(mx1, fmaxf(sacc[nt][2], sacc[nt][3]));
    }
    mx0 = fmaxf(mx0, __shfl_xor_sync(0xffffffffu, mx0, 1));
    mx0 = fmaxf(mx0, __shfl_xor_sync(0xffffffffu, mx0, 2));
    mx1 = fmaxf(mx1, __shfl_xor_sync(0xffffffffu, mx1, 1));
    mx1 = fmaxf(mx1, __shfl_xor_sync(0xffffffffu, mx1, 2));
    const float mnew0 = fmaxf(m_prev0, mx0);
    const float mnew1 = fmaxf(m_prev1, mx1);
    const float f0 = expf(m_prev0 - mnew0);
    const float f1 = expf(m_prev1 - mnew1);
    float rsum0 = 0.f, rsum1 = 0.f;
    __half* const Pw0 = Ph + (warp * 16 + lg) * AQ;
    __half* const Pw1 = Pw0 + 8 * AQ;
#pragma unroll
    for (int nt = 0; nt < 8; nt++) {
      __half2 hp0 = __floats2half2_rn(expf(sacc[nt][0] - mnew0),
                                      expf(sacc[nt][1] - mnew0));
      __half2 hp1 = __floats2half2_rn(expf(sacc[nt][2] - mnew1),
                                      expf(sacc[nt][3] - mnew1));
      const float2 f0v = __half22float2(hp0);
      const float2 f1v = __half22float2(hp1);
      rsum0 += f0v.x + f0v.y;
      rsum1 += f1v.x + f1v.y;
      *reinterpret_cast<__half2*>(Pw0 + nt * 8 + 2 * lt) = hp0;
      *reinterpret_cast<__half2*>(Pw1 + nt * 8 + 2 * lt) = hp1;
    }
    rsum0 += __shfl_xor_sync(0xffffffffu, rsum0, 1);
    rsum0 += __shfl_xor_sync(0xffffffffu, rsum0, 2);
    rsum1 += __shfl_xor_sync(0xffffffffu, rsum1, 1);
    rsum1 += __shfl_xor_sync(0xffffffffu, rsum1, 2);
    l0 = l0 * f0 + rsum0;
    l1 = l1 * f1 + rsum1;
    m_prev0 = mnew0; m_prev1 = mnew1;
#pragma unroll
    for (int nt = 0; nt < 8; nt++) {
      oacc[nt][0] *= f0; oacc[nt][1] *= f0;
      oacc[nt][2] *= f1; oacc[nt][3] *= f1;
    }
    __syncwarp();

    // O += P V  (A = P[16 x 64 kv], B = Vt[d][kv])
#pragma unroll
    for (int cc = 0; cc < 4; cc++) {
      const uint32_t kboff = (uint32_t)(cc * 32);
      uint32_t a0, a1, a2, a3;
      ldsm4(a0, a1, a2, a3, pb + arow_off + kboff);
#pragma unroll
      for (int j = 0; j < 4; j++) {
        uint32_t b0, b1, b2, b3;
        ldsm4(b0, b1, b2, b3, vb + brow_off[j] + kboff);
        HMMA16(oacc[2 * j + 0], a0, a1, a2, a3, b0, b1);
        HMMA16(oacc[2 * j + 1], a0, a1, a2, a3, b2, b3);
      }
    }
  }

  const float inv0 = 1.0f / l0;
  const float inv1 = 1.0f / l1;
  const int r0 = q0 + warp * 16 + lg;
  const int r1 = r0 + 8;
#pragma unroll
  for (int nt = 0; nt < 8; nt++) {
    const int d = h * 64 + nt * 8 + 2 * lt;
    *reinterpret_cast<__half2*>(out + (size_t)(b * 1024 + r0) * 1024 + d) =
        __floats2half2_rn(oacc[nt][0] * inv0, oacc[nt][1] * inv0);
    *reinterpret_cast<__half2*>(out + (size_t)(b * 1024 + r1) * 1024 + d) =
        __floats2half2_rn(oacc[nt][2] * inv1, oacc[nt][3] * inv1);
  }
}

// ---------------- launch ----------------
extern "C" void kernel_launch(void* const* d_in, const int* in_sizes, int n_in,
                              void* d_out, int out_size) {
  const float* x = (const float*)d_in[0];
  const float* ln1w = (const float*)d_in[1];
  const float* ln1b = (const float*)d_in[2];
  const float* qkvw = (const float*)d_in[3];
  const float* qkvb = (const float*)d_in[4];
  const float* outw = (const float*)d_in[5];
  const float* outb = (const float*)d_in[6];
  const float* ln2w = (const float*)d_in[7];
  const float* ln2b = (const float*)d_in[8];
  const float* fc1w = (const float*)d_in[9];
  const float* fc1b = (const float*)d_in[10];
  const float* fc2w = (const float*)d_in[11];
  const float* fc2b = (const float*)d_in[12];
  float* out = (float*)d_out;

  __half *h, *qkv, *attno, *ff, *wq, *wo, *w1, *w2;
  float* x1;
  cudaGetSymbolAddress((void**)&h, g_h);
  cudaGetSymbolAddress((void**)&qkv, g_qkv);
  cudaGetSymbolAddress((void**)&attno, g_attno);
  cudaGetSymbolAddress((void**)&x1, g_x1);
  cudaGetSymbolAddress((void**)&ff, g_ff);
  cudaGetSymbolAddress((void**)&wq, g_wq);
  cudaGetSymbolAddress((void**)&wo, g_wo);
  cudaGetSymbolAddress((void**)&w1, g_w1);
  cudaGetSymbolAddress((void**)&w2, g_w2);

  cudaFuncSetAttribute(attn_h,
                       cudaFuncAttributeMaxDynamicSharedMemorySize, ATTN_SMEM);
  cudaFuncSetAttribute((const void*)mma_nt<0, __half>,
                       cudaFuncAttributeMaxDynamicSharedMemorySize, MMA_SMEM);
  cudaFuncSetAttribute((const void*)mma_nt<1, float>,
                       cudaFuncAttributeMaxDynamicSharedMemorySize, MMA_SMEM);
  cudaFuncSetAttribute((const void*)mma_nt<2, __half>,
                       cudaFuncAttributeMaxDynamicSharedMemorySize, MMA_SMEM);

  // fp16 weight copies
  to_half_kernel<<<(3 * DIM * DIM / 4 + 255) / 256, 256>>>(qkvw, wq, 3 * DIM * DIM / 4);
  to_half_kernel<<<(DIM * DIM / 4 + 255) / 256, 256>>>(outw, wo, DIM * DIM / 4);
  to_half_kernel<<<(4096 * DIM / 4 + 255) / 256, 256>>>(fc1w, w1, 4096 * DIM / 4);
  to_half_kernel<<<(DIM * 4096 / 4 + 255) / 256, 256>>>(fc2w, w2, DIM * 4096 / 4);

  // LN1 -> fp16
  ln_kernel<<<NTOK, 256>>>(x, ln1w, ln1b, h);
  // QKV -> fp16
  mma_nt<0, __half><<<dim3(3072 / 128, NTOK / 128), 256, MMA_SMEM>>>(
      h, wq, qkvb, nullptr, qkv, NTOK, 3072, 1024);
  // attention -> fp16
  attn_h<<<dim3(1024 / 128, 128), 256, ATTN_SMEM>>>(qkv, attno);
  // out projection + residual -> fp32
  mma_nt<1, float><<<dim3(1024 / 128, NTOK / 128), 256, MMA_SMEM>>>(
      attno, wo, outb, x, x1, NTOK, 1024, 1024);
  // LN2 -> fp16
  ln_kernel<<<NTOK, 256>>>(x1, ln2w, ln2b, h);
  // FC1 + GELU -> fp16
  mma_nt<2, __half><<<dim3(4096 / 128, NTOK / 128), 256, MMA_SMEM>>>(
      h, w1, fc1b, nullptr, ff, NTOK, 4096, 1024);
  // FC2 + residual -> fp32 output
  mma_nt<1, float><<<dim3(1024 / 128, NTOK / 128), 256, MMA_SMEM>>>(
      ff, w2, fc2b, x1, out, NTOK, 1024, 4096);
}

// round 9
// speedup vs baseline: 2.0430x; 1.0146x over previous
#include <cuda_runtime.h>
#include <cuda_fp16.h>
#include <math.h>
#include <stdint.h>

#define NTOK 8192
#define DIM 1024

// ---------------- scratch (device globals; no allocation) ----------------
__device__ __half g_h[NTOK * DIM];
__device__ __half g_qkv[NTOK * 3 * DIM];
__device__ __half g_attno[NTOK * DIM];
__device__ float g_x1[NTOK * DIM];
__device__ __half g_ff[NTOK * 4096];
__device__ __half g_wq[3 * DIM * DIM];
__device__ __half g_wo[DIM * DIM];
__device__ __half g_w1[4096 * DIM];
__device__ __half g_w2[DIM * 4096];

__device__ __forceinline__ void cp16(uint32_t dst, const void* src) {
  asm volatile("cp.async.cg.shared.global [%0], [%1], 16;" ::"r"(dst), "l"(src));
}

__device__ __forceinline__ void ldsm4(uint32_t& r0, uint32_t& r1, uint32_t& r2,
                                      uint32_t& r3, uint32_t addr) {
  asm volatile(
      "ldmatrix.sync.aligned.m8n8.x4.shared.b16 {%0,%1,%2,%3}, [%4];"
      : "=r"(r0), "=r"(r1), "=r"(r2), "=r"(r3)
      : "r"(addr));
}

#define HMMA16(d, a0, a1, a2, a3, b0, b1)                                    \
  asm volatile(                                                              \
      "mma.sync.aligned.m16n8k16.row.col.f32.f16.f16.f32 "                   \
      "{%0,%1,%2,%3}, {%4,%5,%6,%7}, {%8,%9}, {%0,%1,%2,%3};"                \
      : "+f"((d)[0]), "+f"((d)[1]), "+f"((d)[2]), "+f"((d)[3])               \
      : "r"(a0), "r"(a1), "r"(a2), "r"(a3), "r"(b0), "r"(b1))

// ---------------- weight conversion: fp32 -> fp16 ----------------
__global__ void __launch_bounds__(256) to_half_kernel(
    const float* __restrict__ in, __half* __restrict__ out, int n4) {
  const int i = blockIdx.x * 256 + threadIdx.x;
  if (i < n4) {
    const float4 v = reinterpret_cast<const float4*>(in)[i];
    __half2 h0 = __floats2half2_rn(v.x, v.y);
    __half2 h1 = __floats2half2_rn(v.z, v.w);
    uint2 pk;
    pk.x = *reinterpret_cast<uint32_t*>(&h0);
    pk.y = *reinterpret_cast<uint32_t*>(&h1);
    reinterpret_cast<uint2*>(out)[i] = pk;
  }
}

// ---------------- LayerNorm (fp16 output) ----------------
__global__ void __launch_bounds__(256) ln_kernel(
    const float* __restrict__ in, const float* __restrict__ w,
    const float* __restrict__ b, __half* __restrict__ out) {
  const int row = blockIdx.x;
  const int tid = threadIdx.x;
  const float4 v = reinterpret_cast<const float4*>(in + (size_t)row * DIM)[tid];
  float s = v.x + v.y + v.z + v.w;
  float sq = v.x * v.x + v.y * v.y + v.z * v.z + v.w * v.w;
#pragma unroll
  for (int o = 16; o > 0; o >>= 1) {
    s += __shfl_xor_sync(0xffffffffu, s, o);
    sq += __shfl_xor_sync(0xffffffffu, sq, o);
  }
  __shared__ float rs[8], rq[8];
  const int warp = tid >> 5, lane = tid & 31;
  if (lane == 0) { rs[warp] = s; rq[warp] = sq; }
  __syncthreads();
  float st = 0.f, sqt = 0.f;
#pragma unroll
  for (int i = 0; i < 8; i++) { st += rs[i]; sqt += rq[i]; }
  const float mu = st * (1.0f / DIM);
  const float var = sqt * (1.0f / DIM) - mu * mu;
  const float rstd = rsqrtf(var + 1e-5f);
  const float4 wv = reinterpret_cast<const float4*>(w)[tid];
  const float4 bv = reinterpret_cast<const float4*>(b)[tid];
  __half2 h0 = __floats2half2_rn((v.x - mu) * rstd * wv.x + bv.x,
                                 (v.y - mu) * rstd * wv.y + bv.y);
  __half2 h1 = __floats2half2_rn((v.z - mu) * rstd * wv.z + bv.z,
                                 (v.w - mu) * rstd * wv.w + bv.w);
  uint2 pk;
  pk.x = *reinterpret_cast<uint32_t*>(&h0);
  pk.y = *reinterpret_cast<uint32_t*>(&h1);
  reinterpret_cast<uint2*>(out + (size_t)row * DIM)[tid] = pk;
}

// ---------------- fp16 GEMM NT: 4 warps, 64x64 warp tiles ----------------
// EPI: 0 = bias, 1 = bias + residual(fp32), 2 = bias + exact GELU
// CTA tile 128x128x64, 128 threads, warp grid 2x2, m16n8k16 + ldmatrix.
#define HSTR 72
#define HSTAGE (256 * HSTR)
#define MMA_SMEM (2 * HSTAGE * 2)

template <int EPI, typename TO>
__global__ void __launch_bounds__(128, 2) mma_nt(
    const __half* __restrict__ A, const __half* __restrict__ W,
    const float* __restrict__ bias, const float* __restrict__ res,
    TO* __restrict__ C, int M, int N, int K) {
  extern __shared__ __half smh[];
  const uint32_t smb = (uint32_t)__cvta_generic_to_shared(smh);

  const int bm = blockIdx.y * 128;
  const int bn = blockIdx.x * 128;
  const int tid = threadIdx.x;
  const int lane = tid & 31;
  const int warp = tid >> 5;
  const int wm = (warp >> 1) * 64;
  const int wn = (warp & 1) * 64;
  const int lg = lane >> 2;
  const int lt = lane & 3;

  float acc[4][8][4];
#pragma unroll
  for (int mt = 0; mt < 4; mt++)
#pragma unroll
    for (int nt = 0; nt < 8; nt++)
#pragma unroll
      for (int i = 0; i < 4; i++) acc[mt][nt][i] = 0.f;

  // ldmatrix per-thread byte offsets (within a stage buffer)
  const uint32_t aoff =
      (uint32_t)(((wm + (lane & 15)) * HSTR + ((lane >> 4) & 1) * 8) * 2);
  uint32_t boff[4];
#pragma unroll
  for (int j = 0; j < 4; j++)
    boff[j] = (uint32_t)(((wn + j * 16 + ((lane >> 4) & 1) * 8 + (lane & 7)) * HSTR +
                          ((lane >> 3) & 1) * 8) * 2) +
              (uint32_t)(128 * HSTR * 2);

  const int lr = tid >> 3;        // 0..15 (+16*i)
  const int lch = (tid & 7) * 8;  // half-col 0,8,...,56
  const int NIT = K >> 6;

  auto load_stage = [&](int s, int k0) {
    const uint32_t abase = smb + (uint32_t)(s * HSTAGE) * 2u;
    const uint32_t bbase = abase + (uint32_t)(128 * HSTR) * 2u;
#pragma unroll
    for (int i = 0; i < 8; i++) {
      const int row = lr + i * 16;
      cp16(abase + (uint32_t)(row * HSTR + lch) * 2u,
           A + (size_t)(bm + row) * K + k0 + lch);
      cp16(bbase + (uint32_t)(row * HSTR + lch) * 2u,
           W + (size_t)(bn + row) * K + k0 + lch);
    }
    asm volatile("cp.async.commit_group;");
  };

  load_stage(0, 0);

  for (int it = 0; it < NIT; it++) {
    if (it + 1 < NIT) {
      load_stage((it + 1) & 1, (it + 1) << 6);
      asm volatile("cp.async.wait_group 1;");
    } else {
      asm volatile("cp.async.wait_group 0;");
    }
    __syncthreads();

    const uint32_t buf = smb + (uint32_t)((it & 1) * HSTAGE) * 2u;
#pragma unroll
    for (int ks = 0; ks < 4; ks++) {
      const uint32_t kb = (uint32_t)(ks * 32);  // 16 halves
      uint32_t a[4][4];
#pragma unroll
      for (int mt = 0; mt < 4; mt++)
        ldsm4(a[mt][0], a[mt][1], a[mt][2], a[mt][3],
              buf + aoff + kb + (uint32_t)(mt * 16 * HSTR * 2));
#pragma unroll
      for (int j = 0; j < 4; j++) {
        uint32_t b0, b1, b2, b3;
        ldsm4(b0, b1, b2, b3, buf + boff[j] + kb);
#pragma unroll
        for (int mt = 0; mt < 4; mt++) {
          HMMA16(acc[mt][2 * j + 0], a[mt][0], a[mt][1], a[mt][2], a[mt][3], b0, b1);
          HMMA16(acc[mt][2 * j + 1], a[mt][0], a[mt][1], a[mt][2], a[mt][3], b2, b3);
        }
      }
    }
    __syncthreads();
  }

  // epilogue
#pragma unroll
  for (int mt = 0; mt < 4; mt++) {
#pragma unroll
    for (int nt = 0; nt < 8; nt++) {
      const int c0 = bn + wn + nt * 8 + 2 * lt;
      const float2 bb = *reinterpret_cast<const float2*>(bias + c0);
#pragma unroll
      for (int rh = 0; rh < 2; rh++) {
        const int row = bm + wm + mt * 16 + lg + rh * 8;
        float ox = acc[mt][nt][rh * 2 + 0] + bb.x;
        float oy = acc[mt][nt][rh * 2 + 1] + bb.y;
        if (EPI == 1) {
          const float2 rr = *reinterpret_cast<const float2*>(res + (size_t)row * N + c0);
          ox += rr.x; oy += rr.y;
        } else if (EPI == 2) {
          ox = 0.5f * ox * (1.0f + erff(ox * 0.70710678118654752f));
          oy = 0.5f * oy * (1.0f + erff(oy * 0.70710678118654752f));
        }
        if (sizeof(TO) == 2) {
          __half2 hv = __floats2half2_rn(ox, oy);
          *reinterpret_cast<__half2*>((__half*)C + (size_t)row * N + c0) = hv;
        } else {
          *reinterpret_cast<float2*>((float*)C + (size_t)row * N + c0) =
              make_float2(ox, oy);
        }
      }
    }
  }
}

// ---------------- fp16 flash attention with ldmatrix (R8, unchanged) -------
#define AQ 72
#define ATTN_SMEM ((128 * AQ + 64 * AQ + 64 * AQ + 128 * AQ) * 2)

__global__ void __launch_bounds__(256) attn_h(
    const __half* __restrict__ qkv, __half* __restrict__ out) {
  extern __shared__ __half smh[];
  const uint32_t smb = (uint32_t)__cvta_generic_to_shared(smh);
  const uint32_t qb = smb;
  const uint32_t kb = qb + 128 * AQ * 2;
  const uint32_t vb = kb + 64 * AQ * 2;
  const uint32_t pb = vb + 64 * AQ * 2;
  __half* const Qh = smh;
  __half* const Kh = Qh + 128 * AQ;
  __half* const Vt = Kh + 64 * AQ;
  __half* const Ph = Vt + 64 * AQ;

  const int tid = threadIdx.x;
  const int lane = tid & 31;
  const int warp = tid >> 5;
  const int lg = lane >> 2;
  const int lt = lane & 3;
  const int bh = blockIdx.y;
  const int b = bh >> 4, h = bh & 15;
  const int q0 = blockIdx.x * 128;
  const size_t base = (size_t)b * 1024 * 3072 + (size_t)h * 64;

  const uint32_t arow_off =
      (uint32_t)(((warp * 16 + (lane & 15)) * AQ + ((lane >> 4) & 1) * 8) * 2);
  uint32_t brow_off[4];
#pragma unroll
  for (int j = 0; j < 4; j++)
    brow_off[j] = (uint32_t)(((j * 16 + ((lane >> 4) & 1) * 8 + (lane & 7)) * AQ +
                              ((lane >> 3) & 1) * 8) * 2);

  {
    const int row = tid >> 1;
    const int c = (tid & 1) * 32;
    const __half2 sc = __float2half2_rn(0.125f);
    const __half* src = qkv + base + (size_t)(q0 + row) * 3072 + c;
    __half* dst = Qh + row * AQ + c;
#pragma unroll
    for (int i = 0; i < 4; i++) {
      uint4 v = *reinterpret_cast<const uint4*>(src + i * 8);
      __half2* p = reinterpret_cast<__half2*>(&v);
      p[0] = __hmul2(p[0], sc); p[1] = __hmul2(p[1], sc);
      p[2] = __hmul2(p[2], sc); p[3] = __hmul2(p[3], sc);
      *reinterpret_cast<uint4*>(dst + i * 8) = v;
    }
  }

  float m_prev0 = -INFINITY, m_prev1 = -INFINITY;
  float l0 = 0.f, l1 = 0.f;
  float oacc[8][4];
#pragma unroll
  for (int nt = 0; nt < 8; nt++)
#pragma unroll
    for (int i = 0; i < 4; i++) oacc[nt][i] = 0.f;

  for (int t = 0; t < 16; t++) {
    __syncthreads();
    {
      const int row = tid >> 2;
      const int c = (tid & 3) * 16;
      const __half* ksrc = qkv + base + (size_t)(t * 64 + row) * 3072 + 1024 + c;
      const __half* vsrc = ksrc + 1024;
      *reinterpret_cast<uint4*>(Kh + row * AQ + c) =
          *reinterpret_cast<const uint4*>(ksrc);
      *reinterpret_cast<uint4*>(Kh + row * AQ + c + 8) =
          *reinterpret_cast<const uint4*>(ksrc + 8);
      uint4 v0 = *reinterpret_cast<const uint4*>(vsrc);
      uint4 v1 = *reinterpret_cast<const uint4*>(vsrc + 8);
      const __half* hv0 = reinterpret_cast<const __half*>(&v0);
      const __half* hv1 = reinterpret_cast<const __half*>(&v1);
#pragma unroll
      for (int i = 0; i < 8; i++) Vt[(c + i) * AQ + row] = hv0[i];
#pragma unroll
      for (int i = 0; i < 8; i++) Vt[(c + 8 + i) * AQ + row] = hv1[i];
    }
    __syncthreads();

    float sacc[8][4];
#pragma unroll
    for (int nt = 0; nt < 8; nt++)
#pragma unroll
      for (int i = 0; i < 4; i++) sacc[nt][i] = 0.f;

#pragma unroll
    for (int kc = 0; kc < 4; kc++) {
      const uint32_t kboff = (uint32_t)(kc * 32);
      uint32_t a0, a1, a2, a3;
      ldsm4(a0, a1, a2, a3, qb + arow_off + kboff);
#pragma unroll
      for (int j = 0; j < 4; j++) {
        uint32_t b0, b1, b2, b3;
        ldsm4(b0, b1, b2, b3, kb + brow_off[j] + kboff);
        HMMA16(sacc[2 * j + 0], a0, a1, a2, a3, b0, b1);
        HMMA16(sacc[2 * j + 1], a0, a1, a2, a3, b2, b3);
      }
    }

    float mx0 = -INFINITY, mx1 = -INFINITY;
#pragma unroll
    for (int nt = 0; nt < 8; nt++) {
      mx0 = fmaxf(mx0, fmaxf(sacc[nt][0], sacc[nt][1]));
      mx1 = fmaxf(mx1, fmaxf(sacc[nt][2], sacc[nt][3]));
    }
    mx0 = fmaxf(mx0, __shfl_xor_sync(0xffffffffu, mx0, 1));
    mx0 = fmaxf(mx0, __shfl_xor_sync(0xffffffffu, mx0, 2));
    mx1 = fmaxf(mx1, __shfl_xor_sync(0xffffffffu, mx1, 1));
    mx1 = fmaxf(mx1, __shfl_xor_sync(0xffffffffu, mx1, 2));
    const float mnew0 = fmaxf(m_prev0, mx0);
    const float mnew1 = fmaxf(m_prev1, mx1);
    const float f0 = expf(m_prev0 - mnew0);
    const float f1 = expf(m_prev1 - mnew1);
    float rsum0 = 0.f, rsum1 = 0.f;
    __half* const Pw0 = Ph + (warp * 16 + lg) * AQ;
    __half* const Pw1 = Pw0 + 8 * AQ;
#pragma unroll
    for (int nt = 0; nt < 8; nt++) {
      __half2 hp0 = __floats2half2_rn(expf(sacc[nt][0] - mnew0),
                                      expf(sacc[nt][1] - mnew0));
      __half2 hp1 = __floats2half2_rn(expf(sacc[nt][2] - mnew1),
                                      expf(sacc[nt][3] - mnew1));
      const float2 f0v = __half22float2(hp0);
      const float2 f1v = __half22float2(hp1);
      rsum0 += f0v.x + f0v.y;
      rsum1 += f1v.x + f1v.y;
      *reinterpret_cast<__half2*>(Pw0 + nt * 8 + 2 * lt) = hp0;
      *reinterpret_cast<__half2*>(Pw1 + nt * 8 + 2 * lt) = hp1;
    }
    rsum0 += __shfl_xor_sync(0xffffffffu, rsum0, 1);
    rsum0 += __shfl_xor_sync(0xffffffffu, rsum0, 2);
    rsum1 += __shfl_xor_sync(0xffffffffu, rsum1, 1);
    rsum1 += __shfl_xor_sync(0xffffffffu, rsum1, 2);
    l0 = l0 * f0 + rsum0;
    l1 = l1 * f1 + rsum1;
    m_prev0 = mnew0; m_prev1 = mnew1;
#pragma unroll
    for (int nt = 0; nt < 8; nt++) {
      oacc[nt][0] *= f0; oacc[nt][1] *= f0;
      oacc[nt][2] *= f1; oacc[nt][3] *= f1;
    }
    __syncwarp();

#pragma unroll
    for (int cc = 0; cc < 4; cc++) {
      const uint32_t kboff = (uint32_t)(cc * 32);
      uint32_t a0, a1, a2, a3;
      ldsm4(a0, a1, a2, a3, pb + arow_off + kboff);
#pragma unroll
      for (int j = 0; j < 4; j++) {
        uint32_t b0, b1, b2, b3;
        ldsm4(b0, b1, b2, b3, vb + brow_off[j] + kboff);
        HMMA16(oacc[2 * j + 0], a0, a1, a2, a3, b0, b1);
        HMMA16(oacc[2 * j + 1], a0, a1, a2, a3, b2, b3);
      }
    }
  }

  const float inv0 = 1.0f / l0;
  const float inv1 = 1.0f / l1;
  const int r0 = q0 + warp * 16 + lg;
  const int r1 = r0 + 8;
#pragma unroll
  for (int nt = 0; nt < 8; nt++) {
    const int d = h * 64 + nt * 8 + 2 * lt;
    *reinterpret_cast<__half2*>(out + (size_t)(b * 1024 + r0) * 1024 + d) =
        __floats2half2_rn(oacc[nt][0] * inv0, oacc[nt][1] * inv0);
    *reinterpret_cast<__half2*>(out + (size_t)(b * 1024 + r1) * 1024 + d) =
        __floats2half2_rn(oacc[nt][2] * inv1, oacc[nt][3] * inv1);
  }
}

// ---------------- launch ----------------
extern "C" void kernel_launch(void* const* d_in, const int* in_sizes, int n_in,
                              void* d_out, int out_size) {
  const float* x = (const float*)d_in[0];
  const float* ln1w = (const float*)d_in[1];
  const float* ln1b = (const float*)d_in[2];
  const float* qkvw = (const float*)d_in[3];
  const float* qkvb = (const float*)d_in[4];
  const float* outw = (const float*)d_in[5];
  const float* outb = (const float*)d_in[6];
  const float* ln2w = (const float*)d_in[7];
  const float* ln2b = (const float*)d_in[8];
  const float* fc1w = (const float*)d_in[9];
  const float* fc1b = (const float*)d_in[10];
  const float* fc2w = (const float*)d_in[11];
  const float* fc2b = (const float*)d_in[12];
  float* out = (float*)d_out;

  __half *h, *qkv, *attno, *ff, *wq, *wo, *w1, *w2;
  float* x1;
  cudaGetSymbolAddress((void**)&h, g_h);
  cudaGetSymbolAddress((void**)&qkv, g_qkv);
  cudaGetSymbolAddress((void**)&attno, g_attno);
  cudaGetSymbolAddress((void**)&x1, g_x1);
  cudaGetSymbolAddress((void**)&ff, g_ff);
  cudaGetSymbolAddress((void**)&wq, g_wq);
  cudaGetSymbolAddress((void**)&wo, g_wo);
  cudaGetSymbolAddress((void**)&w1, g_w1);
  cudaGetSymbolAddress((void**)&w2, g_w2);

  cudaFuncSetAttribute(attn_h,
                       cudaFuncAttributeMaxDynamicSharedMemorySize, ATTN_SMEM);
  cudaFuncSetAttribute((const void*)mma_nt<0, __half>,
                       cudaFuncAttributeMaxDynamicSharedMemorySize, MMA_SMEM);
  cudaFuncSetAttribute((const void*)mma_nt<1, float>,
                       cudaFuncAttributeMaxDynamicSharedMemorySize, MMA_SMEM);
  cudaFuncSetAttribute((const void*)mma_nt<2, __half>,
                       cudaFuncAttributeMaxDynamicSharedMemorySize, MMA_SMEM);

  // fp16 weight copies
  to_half_kernel<<<(3 * DIM * DIM / 4 + 255) / 256, 256>>>(qkvw, wq, 3 * DIM * DIM / 4);
  to_half_kernel<<<(DIM * DIM / 4 + 255) / 256, 256>>>(outw, wo, DIM * DIM / 4);
  to_half_kernel<<<(4096 * DIM / 4 + 255) / 256, 256>>>(fc1w, w1, 4096 * DIM / 4);
  to_half_kernel<<<(DIM * 4096 / 4 + 255) / 256, 256>>>(fc2w, w2, DIM * 4096 / 4);

  // LN1 -> fp16
  ln_kernel<<<NTOK, 256>>>(x, ln1w, ln1b, h);
  // QKV -> fp16
  mma_nt<0, __half><<<dim3(3072 / 128, NTOK / 128), 128, MMA_SMEM>>>(
      h, wq, qkvb, nullptr, qkv, NTOK, 3072, 1024);
  // attention -> fp16
  attn_h<<<dim3(1024 / 128, 128), 256, ATTN_SMEM>>>(qkv, attno);
  // out projection + residual -> fp32
  mma_nt<1, float><<<dim3(1024 / 128, NTOK / 128), 128, MMA_SMEM>>>(
      attno, wo, outb, x, x1, NTOK, 1024, 1024);
  // LN2 -> fp16
  ln_kernel<<<NTOK, 256>>>(x1, ln2w, ln2b, h);
  // FC1 + GELU -> fp16
  mma_nt<2, __half><<<dim3(4096 / 128, NTOK / 128), 128, MMA_SMEM>>>(
      h, w1, fc1b, nullptr, ff, NTOK, 4096, 1024);
  // FC2 + residual -> fp32 output
  mma_nt<1, float><<<dim3(1024 / 128, NTOK / 128), 128, MMA_SMEM>>>(
      ff, w2, fc2b, x1, out, NTOK, 1024, 4096);
}